// round 11
// baseline (speedup 1.0000x reference)
#include <cuda_runtime.h>
#include <cuda_bf16.h>
#include <cstdint>

#define HD 128
#define WPB 8                       // warps per CTA
#define NTHREADS (WPB * 32)
#define GRID1 740                   // 148 SMs * 5 CTAs (regs=48 -> 5 CTAs/SM resident)
#define NWTOT (GRID1 * WPB)         // 5920 worker warps
#define BMAX 2048                   // scratch sized for up to 2048 segments

// ---- persistent scratch (zero-initialized at module load) ----
// Invariant: for an EMPTY segment s nothing ever writes g_seg_bounds[s] (any
// run, any replay) so it stays {0,0}; a NON-EMPTY segment gets .y = j >= 1
// from exactly one warp (and .x = start from exactly one warp). Hence
// g_seg_bounds[s].y == 0 <=> empty; no init kernel needed.
__device__ float g_head_num[NWTOT * HD];
__device__ float g_tail_num[NWTOT * HD];
__device__ float g_head_d[NWTOT];
__device__ float g_tail_d[NWTOT];
__device__ int   g_head_seg[NWTOT];
__device__ int   g_tail_seg[NWTOT];
__device__ float g_num_acc[BMAX * HD];   // direct-stored exclusive segments
__device__ float g_d_acc[BMAX];
__device__ int2  g_seg_bounds[BMAX];     // .x = start row, .y = end row (0 => empty)

// K1: each global warp g owns contiguous rows [g*RPW, min((g+1)*RPW, N)).
// Splits its range into same-segment runs; accumulates d = sum exp(s_i),
// num = sum exp(s_i)*x_i per run; flushes each run to either the exclusive
// per-segment slot or the warp's head/tail partial slot. Records the TRUE
// segment start/end rows (single writer per 4B word) so K2 needs no search.
// Ends with a PDL trigger so K2's launch overlaps K1's drain.
__global__ void __launch_bounds__(NTHREADS, 5)
gap_k1(const float* __restrict__ x,
       const int*   __restrict__ batch,
       const float* __restrict__ W,
       int N)
{
    const int wid  = threadIdx.x >> 5;
    const int lane = threadIdx.x & 31;
    const int g    = blockIdx.x * WPB + wid;

    const int rpw = (N + NWTOT - 1) / NWTOT;
    const long long rl = (long long)g * rpw;

    int hseg = -1, tseg = -1;

    if (rl < N) {
        const int lo = (int)rl;
        const int hi = min(lo + rpw, N);
        const float4 Wv = *reinterpret_cast<const float4*>(W + lane * 4);
        const long long col = (long long)lane * 4;

        int i = lo;
        while (i < hi) {
            const int seg = batch[i];
            // upper_bound(seg) in (i, hi)
            int a = i + 1, b = hi;
            while (a < b) { int m = (a + b) >> 1; if (batch[m] <= seg) a = m + 1; else b = m; }
            const int j = a;

            float  d = 0.0f;
            float4 num = make_float4(0.0f, 0.0f, 0.0f, 0.0f);

            int r = i;
            // 4 consecutive rows per iter: 4 independent LDG.128, 2KB contiguous
            for (; r + 4 <= j; r += 4) {
                const float4 x0 = __ldcs(reinterpret_cast<const float4*>(x + (long long)(r    ) * HD + col));
                const float4 x1 = __ldcs(reinterpret_cast<const float4*>(x + (long long)(r + 1) * HD + col));
                const float4 x2 = __ldcs(reinterpret_cast<const float4*>(x + (long long)(r + 2) * HD + col));
                const float4 x3 = __ldcs(reinterpret_cast<const float4*>(x + (long long)(r + 3) * HD + col));

                float p0 = x0.x * Wv.x + x0.y * Wv.y + x0.z * Wv.z + x0.w * Wv.w;
                float p1 = x1.x * Wv.x + x1.y * Wv.y + x1.z * Wv.z + x1.w * Wv.w;
                float p2 = x2.x * Wv.x + x2.y * Wv.y + x2.z * Wv.z + x2.w * Wv.w;
                float p3 = x3.x * Wv.x + x3.y * Wv.y + x3.z * Wv.z + x3.w * Wv.w;
                #pragma unroll
                for (int o = 16; o > 0; o >>= 1) {
                    p0 += __shfl_xor_sync(0xffffffffu, p0, o);
                    p1 += __shfl_xor_sync(0xffffffffu, p1, o);
                    p2 += __shfl_xor_sync(0xffffffffu, p2, o);
                    p3 += __shfl_xor_sync(0xffffffffu, p3, o);
                }
                const float e0 = __expf(p0);
                const float e1 = __expf(p1);
                const float e2 = __expf(p2);
                const float e3 = __expf(p3);
                d += (e0 + e1) + (e2 + e3);
                num.x += e0 * x0.x + e1 * x1.x + e2 * x2.x + e3 * x3.x;
                num.y += e0 * x0.y + e1 * x1.y + e2 * x2.y + e3 * x3.y;
                num.z += e0 * x0.z + e1 * x1.z + e2 * x2.z + e3 * x3.z;
                num.w += e0 * x0.w + e1 * x1.w + e2 * x2.w + e3 * x3.w;
            }
            for (; r < j; r++) {
                const float4 xv = __ldcs(reinterpret_cast<const float4*>(x + (long long)r * HD + col));
                float p = xv.x * Wv.x + xv.y * Wv.y + xv.z * Wv.z + xv.w * Wv.w;
                #pragma unroll
                for (int o = 16; o > 0; o >>= 1) p += __shfl_xor_sync(0xffffffffu, p, o);
                const float e = __expf(p);
                d += e;
                num.x += e * xv.x; num.y += e * xv.y; num.z += e * xv.z; num.w += e * xv.w;
            }

            const bool sb = (i == lo) && (lo > 0) && (batch[lo - 1] == seg);   // continues before
            const bool ea = (j == hi) && (hi < N) && (batch[hi] == seg);       // continues after

            if (lane == 0) {
                if (!sb) g_seg_bounds[seg].x = i;   // true segment start (unique writer)
                if (!ea) g_seg_bounds[seg].y = j;   // true segment end   (unique writer, j >= 1)
            }

            if (!sb && !ea) {
                // exclusive segment: this warp is the sole contributor
                *reinterpret_cast<float4*>(g_num_acc + (long long)seg * HD + lane * 4) = num;
                if (lane == 0) g_d_acc[seg] = d;
            } else if (sb) {
                hseg = seg;
                *reinterpret_cast<float4*>(g_head_num + (long long)g * HD + lane * 4) = num;
                if (lane == 0) g_head_d[g] = d;
            } else {
                tseg = seg;
                *reinterpret_cast<float4*>(g_tail_num + (long long)g * HD + lane * 4) = num;
                if (lane == 0) g_tail_d[g] = d;
            }
            i = j;
        }
    }
    if (lane == 0) { g_head_seg[g] = hseg; g_tail_seg[g] = tseg; }

    // PDL: allow the dependent K2 launch to begin rolling out now; K2 waits
    // for full K1 completion (and memory flush) via cudaGridDependencySynchronize.
    cudaTriggerProgrammaticLaunchCompletion();
}

// K2: one WARP per segment (8 segments per 256-thread CTA, grid B/8).
// Lane l owns columns [4l, 4l+4) as a float4. Launched with PDL so its
// prologue overlaps K1's tail; first consumes scratch only after
// cudaGridDependencySynchronize. Empty segment: bounds.y == 0 -> zeros.
__global__ void __launch_bounds__(NTHREADS)
gap_k2(float* __restrict__ out, int N, int B)
{
    cudaGridDependencySynchronize();

    const int wid  = threadIdx.x >> 5;
    const int lane = threadIdx.x & 31;
    const int s    = blockIdx.x * WPB + wid;
    if (s >= B) return;

    float4* outv = reinterpret_cast<float4*>(out + (long long)s * HD + lane * 4);

    const int2 bounds = g_seg_bounds[s];          // one 8B load: {start, end}
    if (bounds.y == 0) { *outv = make_float4(0.0f, 0.0f, 0.0f, 0.0f); return; }

    const int rpw = (N + NWTOT - 1) / NWTOT;
    const int glo = bounds.x / rpw;
    const int ghi = (bounds.y - 1) / rpw;

    float4 num = make_float4(0.0f, 0.0f, 0.0f, 0.0f);
    float  d = 0.0f;
    int matches = 0;
    for (int g = glo; g <= ghi; g++) {
        if (g_head_seg[g] == s) {
            const float4 v = *reinterpret_cast<const float4*>(g_head_num + (long long)g * HD + lane * 4);
            num.x += v.x; num.y += v.y; num.z += v.z; num.w += v.w;
            d += g_head_d[g]; matches++;
        }
        if (g_tail_seg[g] == s) {
            const float4 v = *reinterpret_cast<const float4*>(g_tail_num + (long long)g * HD + lane * 4);
            num.x += v.x; num.y += v.y; num.z += v.z; num.w += v.w;
            d += g_tail_d[g]; matches++;
        }
    }
    if (matches == 0) {
        num = *reinterpret_cast<const float4*>(g_num_acc + (long long)s * HD + lane * 4);
        d   = g_d_acc[s];
    }
    const float inv = 1.0f / (d + 1e-16f);
    num.x *= inv; num.y *= inv; num.z *= inv; num.w *= inv;
    *outv = num;
}

extern "C" void kernel_launch(void* const* d_in, const int* in_sizes, int n_in,
                              void* d_out, int out_size)
{
    const float* x     = (const float*)d_in[0];
    // d_in[1] = edge_index (unused by the forward math)
    const int*   batch = (const int*)d_in[2];
    const float* W     = (const float*)d_in[3];
    // d_in[4] = b (zeros; cancels in the softmax)
    float* out = (float*)d_out;

    const int N = in_sizes[2];
    const int B = out_size / HD;

    gap_k1<<<GRID1, NTHREADS>>>(x, batch, W, N);

    // K2 with programmatic dependent launch: rollout overlaps K1's drain.
    cudaLaunchConfig_t cfg = {};
    cfg.gridDim  = dim3((B + WPB - 1) / WPB, 1, 1);
    cfg.blockDim = dim3(NTHREADS, 1, 1);
    cudaLaunchAttribute attrs[1];
    attrs[0].id = cudaLaunchAttributeProgrammaticStreamSerialization;
    attrs[0].val.programmaticStreamSerializationAllowed = 1;
    cfg.attrs = attrs;
    cfg.numAttrs = 1;
    cudaLaunchKernelEx(&cfg, gap_k2, out, N, B);
}